// round 16
// baseline (speedup 1.0000x reference)
#include <cuda_runtime.h>
#include <cuda_bf16.h>
#include <cstdint>

// ---------------- problem constants ----------------
#define BATCH       4096
#define NCLASS      10000
#define NCLASS_PAD  10112           // 79 * 128: minimal cover of NCLASS
#define FEAT        1024

#define TILE_M      128
#define TILE_N      128
#define K_STAGE     64
#define N_STAGES    3
#define K_ITERS     (FEAT / K_STAGE)   // 16

#define A_STAGE_BYTES (TILE_M * K_STAGE * 2)   // 16384
#define B_STAGE_BYTES (TILE_N * K_STAGE * 2)   // 16384
#define STAGE_BYTES   (A_STAGE_BYTES + B_STAGE_BYTES) // 32768

#define M_TILES (BATCH / TILE_M)        // 32
#define N_TILES (NCLASS_PAD / TILE_N)   // 79

// SMEM control offsets
#define OFF_FULL   0      // 3 barriers
#define OFF_EMPTY  32     // 3 barriers
#define OFF_FSQ    64     // 128 floats
#define OFF_CSQ    576    // 128 floats
#define CTRL_BYTES 2048
#define GEMM_SMEM  (CTRL_BYTES + 1024 + N_STAGES * STAGE_BYTES)  // 101376 -> 2 CTAs/SM

// ---------------- device scratch ----------------
__device__ __align__(1024) unsigned char g_feat_bf16[(size_t)M_TILES * K_ITERS * A_STAGE_BYTES]; // 8 MB
__device__ __align__(1024) unsigned char g_cent_bf16[(size_t)N_TILES * K_ITERS * B_STAGE_BYTES]; // ~19.8 MB
__device__ float g_feat_sq[BATCH];
__device__ float g_cent_sq[NCLASS_PAD];

// ---------------- PTX helpers ----------------
__device__ __forceinline__ uint32_t smem_u32(const void* p) {
    uint32_t a;
    asm("{ .reg .u64 t; cvta.to.shared.u64 t, %1; cvt.u32.u64 %0, t; }" : "=r"(a) : "l"(p));
    return a;
}

#define MBARRIER_INIT(addr, cnt) \
    asm volatile("mbarrier.init.shared.b64 [%0], %1;" :: "r"((uint32_t)(addr)), "r"((uint32_t)(cnt)) : "memory")

#define MBARRIER_EXPECT_TX(addr, bytes) \
    asm volatile("mbarrier.arrive.expect_tx.shared.b64 _, [%0], %1;" :: "r"((uint32_t)(addr)), "r"((uint32_t)(bytes)) : "memory")

#define MBARRIER_ARRIVE(addr) \
    asm volatile("mbarrier.arrive.shared.b64 _, [%0];" :: "r"((uint32_t)(addr)) : "memory")

#define MBARRIER_WAIT_PARITY(addr, parity) do {                                   \
    uint32_t _m = (uint32_t)(addr); uint32_t _p = (uint32_t)(parity);             \
    asm volatile(                                                                 \
        "{\n\t.reg .pred P1;\n\t"                                                 \
        "WAIT_LOOP_%=:\n\t"                                                       \
        "mbarrier.try_wait.parity.acquire.cta.shared::cta.b64 P1, [%0], %1, 0x989680;\n\t" \
        "@P1 bra.uni WAIT_DONE_%=;\n\t"                                           \
        "bra.uni WAIT_LOOP_%=;\n\t"                                               \
        "WAIT_DONE_%=:\n\t}"                                                      \
        :: "r"(_m), "r"(_p) : "memory");                                          \
} while (0)

#define FENCE_PROXY_ASYNC() asm volatile("fence.proxy.async.shared::cta;" ::: "memory")

__device__ __forceinline__ void bulk_g2s(uint32_t dst, const void* src, uint32_t bytes, uint32_t mbar) {
    asm volatile(
        "cp.async.bulk.shared::cluster.global.mbarrier::complete_tx::bytes [%0], [%1], %2, [%3];"
        :: "r"(dst), "l"(src), "r"(bytes), "r"(mbar) : "memory");
}

#define LDSM_X4(r, addr) \
    asm volatile("ldmatrix.sync.aligned.m8n8.x4.shared.b16 {%0,%1,%2,%3}, [%4];" \
                 : "=r"((r)[0]), "=r"((r)[1]), "=r"((r)[2]), "=r"((r)[3]) : "r"(addr))

#define MMA16816(d, a, b0, b1) \
    asm volatile("mma.sync.aligned.m16n8k16.row.col.f32.bf16.bf16.f32 " \
                 "{%0,%1,%2,%3}, {%4,%5,%6,%7}, {%8,%9}, {%0,%1,%2,%3};" \
                 : "+f"((d)[0]), "+f"((d)[1]), "+f"((d)[2]), "+f"((d)[3]) \
                 : "r"((a)[0]), "r"((a)[1]), "r"((a)[2]), "r"((a)[3]), "r"(b0), "r"(b1))

__device__ __forceinline__ uint32_t sw128(uint32_t off) { return off ^ ((off >> 3) & 0x70); }

// ---------------- prep: 2 rows/block, 8 bf16 per thread, single STG.128 ----------------
__global__ void __launch_bounds__(256) prep_all(const float* __restrict__ feat,
                                                const float* __restrict__ cent) {
    __shared__ float red[8];
    int t = threadIdx.x;
    int lrow = t >> 7;          // 0..1: row within block (4 warps per row)
    int tt = t & 127;           // thread within row; handles 8 consecutive floats
    int blk = blockIdx.x;
    bool is_feat = blk < (BATCH / 2);
    int r = is_feat ? (blk * 2 + lrow) : ((blk - BATCH / 2) * 2 + lrow);
    const float* src = is_feat ? feat : cent;
    bool valid = is_feat || (r < NCLASS);

    int k = tt * 8;
    float4 v0 = make_float4(0.f, 0.f, 0.f, 0.f), v1 = v0;
    if (valid) {
        const float4* p = reinterpret_cast<const float4*>(src + (size_t)r * FEAT + k);
        v0 = p[0];
        v1 = p[1];
    }
    float s2 = v0.x * v0.x + v0.y * v0.y + v0.z * v0.z + v0.w * v0.w
             + v1.x * v1.x + v1.y * v1.y + v1.z * v1.z + v1.w * v1.w;

    uint4 wv;
    {
        __nv_bfloat162 p01 = __float22bfloat162_rn(make_float2(v0.x, v0.y));
        __nv_bfloat162 p23 = __float22bfloat162_rn(make_float2(v0.z, v0.w));
        __nv_bfloat162 p45 = __float22bfloat162_rn(make_float2(v1.x, v1.y));
        __nv_bfloat162 p67 = __float22bfloat162_rn(make_float2(v1.z, v1.w));
        wv.x = *reinterpret_cast<unsigned int*>(&p01);
        wv.y = *reinterpret_cast<unsigned int*>(&p23);
        wv.z = *reinterpret_cast<unsigned int*>(&p45);
        wv.w = *reinterpret_cast<unsigned int*>(&p67);
    }

    int sgm = k >> 6, c = k & 63;
    uint32_t off = sw128((uint32_t)((r & 127) * 128 + c * 2));  // 16B-aligned; sw128 preserves 16B chunks
    if (is_feat) {
        size_t b = ((size_t)(r >> 7) * K_ITERS + sgm) * (size_t)A_STAGE_BYTES;
        *reinterpret_cast<uint4*>(g_feat_bf16 + b + off) = wv;
    } else {
        size_t b = ((size_t)(r >> 7) * K_ITERS + sgm) * (size_t)B_STAGE_BYTES;
        *reinterpret_cast<uint4*>(g_cent_bf16 + b + off) = wv;
    }

    #pragma unroll
    for (int o = 16; o > 0; o >>= 1) s2 += __shfl_down_sync(0xffffffffu, s2, o);
    if ((t & 31) == 0) red[t >> 5] = s2;
    __syncthreads();
    if (tt == 0) {
        float tot = red[4 * lrow] + red[4 * lrow + 1] + red[4 * lrow + 2] + red[4 * lrow + 3];
        if (is_feat) g_feat_sq[r] = -0.5f * tot;
        else g_cent_sq[r] = -0.5f * tot;
    }
}

// ---------------- main GEMM: R13 config + strength-reduced LDSM addressing ----------------
__global__ void __launch_bounds__(256, 2) lda_gemm(float* __restrict__ out) {
    extern __shared__ unsigned char smem[];
    uint32_t sb = smem_u32(smem);
    int tid = threadIdx.x, l = tid & 31, w = tid >> 5;
    int warp_m = w >> 2;          // 0..1, 64 rows
    int warp_n = w & 3;           // 0..3, 32 cols
    int bx = blockIdx.x;
    int n_tile = bx % N_TILES;
    int m_tile = bx / N_TILES;

    uint32_t dbase = (sb + CTRL_BYTES + 1023u) & ~1023u;
    const unsigned char* abase = g_feat_bf16 + (size_t)m_tile * K_ITERS * A_STAGE_BYTES;
    const unsigned char* bbase = g_cent_bf16 + (size_t)n_tile * K_ITERS * B_STAGE_BYTES;

    // tid0: init barriers, fence, issue prologue immediately (overlaps bias LDGs)
    if (tid == 0) {
        #pragma unroll
        for (int s = 0; s < N_STAGES; s++) {
            MBARRIER_INIT(sb + OFF_FULL + 8 * s, 1);
            MBARRIER_INIT(sb + OFF_EMPTY + 8 * s, 8);
        }
        FENCE_PROXY_ASYNC();
        #pragma unroll
        for (int s = 0; s < N_STAGES; s++) {
            uint32_t full = sb + OFF_FULL + 8 * s;
            MBARRIER_EXPECT_TX(full, STAGE_BYTES);
            bulk_g2s(dbase + s * STAGE_BYTES, abase + (size_t)s * A_STAGE_BYTES,
                     A_STAGE_BYTES, full);
            bulk_g2s(dbase + s * STAGE_BYTES + A_STAGE_BYTES,
                     bbase + (size_t)s * B_STAGE_BYTES, B_STAGE_BYTES, full);
        }
    }

    float* fsq = reinterpret_cast<float*>(smem + OFF_FSQ);
    float* csq = reinterpret_cast<float*>(smem + OFF_CSQ);
    if (tid < 128) {
        fsq[tid] = g_feat_sq[m_tile * TILE_M + tid];
        csq[tid] = g_cent_sq[n_tile * TILE_N + tid];
    }
    __syncthreads();

    float acc[4][4][4];
    #pragma unroll
    for (int i = 0; i < 4; i++)
        #pragma unroll
        for (int j = 0; j < 4; j++)
            #pragma unroll
            for (int q = 0; q < 4; q++) acc[i][j][q] = 0.f;

    int lrow = l & 15;
    int lcol16 = (l >> 4) * 16;
    int a_row = warp_m * 64 + lrow;
    int b_row = warp_n * 32 + lrow;

    uint32_t a_off[4], b_off[2];
    #pragma unroll
    for (int f = 0; f < 4; f++) {
        int ra = a_row + f * 16;
        a_off[f] = (uint32_t)(ra * 128) + ((uint32_t)lcol16 ^ (uint32_t)((ra & 7) << 4));
    }
    #pragma unroll
    for (int f = 0; f < 2; f++) {
        int rb = b_row + f * 16;
        b_off[f] = (uint32_t)(rb * 128) + ((uint32_t)lcol16 ^ (uint32_t)((rb & 7) << 4));
    }

    int slot = 0, ph = 0;
    #pragma unroll 1
    for (int i = 0; i < K_ITERS; i++) {
        MBARRIER_WAIT_PARITY(sb + OFF_FULL + 8 * slot, ph);

        uint32_t Ab = dbase + slot * STAGE_BYTES;
        uint32_t Bb = Ab + A_STAGE_BYTES;

        // Strength reduction: dbase is 1024-aligned and STAGE_BYTES=32768, so
        // Ab/Bb have zero low-10 bits -> (Ab + off) ^ kx == Ab + (off ^ kx)
        // for kx in {0,32,64,96}. Per-stage absolute addresses, per-ks one LOP3.
        uint32_t aa[4], bb[2];
        #pragma unroll
        for (int f = 0; f < 4; f++) aa[f] = Ab + a_off[f];
        #pragma unroll
        for (int f = 0; f < 2; f++) bb[f] = Bb + b_off[f];

        #pragma unroll
        for (int ks = 0; ks < 4; ks++) {
            uint32_t kx = (uint32_t)(ks << 5);
            uint32_t afr[4][4], bfr[2][4];
            #pragma unroll
            for (int f = 0; f < 4; f++) LDSM_X4(afr[f], aa[f] ^ kx);
            #pragma unroll
            for (int f = 0; f < 2; f++) LDSM_X4(bfr[f], bb[f] ^ kx);
            #pragma unroll
            for (int nf2 = 0; nf2 < 2; nf2++) {
                #pragma unroll
                for (int mf = 0; mf < 4; mf++) {
                    MMA16816(acc[mf][nf2 * 2 + 0], afr[mf], bfr[nf2][0], bfr[nf2][2]);
                    MMA16816(acc[mf][nf2 * 2 + 1], afr[mf], bfr[nf2][1], bfr[nf2][3]);
                }
            }
        }
        if (l == 0) MBARRIER_ARRIVE(sb + OFF_EMPTY + 8 * slot);

        if (tid == 0 && i + N_STAGES < K_ITERS) {
            int j = i + N_STAGES;
            MBARRIER_WAIT_PARITY(sb + OFF_EMPTY + 8 * slot, ph);
            uint32_t full = sb + OFF_FULL + 8 * slot;
            MBARRIER_EXPECT_TX(full, STAGE_BYTES);
            bulk_g2s(dbase + slot * STAGE_BYTES, abase + (size_t)j * A_STAGE_BYTES,
                     A_STAGE_BYTES, full);
            bulk_g2s(dbase + slot * STAGE_BYTES + A_STAGE_BYTES,
                     bbase + (size_t)j * B_STAGE_BYTES, B_STAGE_BYTES, full);
        }
        if (++slot == N_STAGES) { slot = 0; ph ^= 1; }
    }

    // epilogue: add fused norm biases, store
    int row0 = warp_m * 64 + (l >> 2);
    int col0 = warp_n * 32 + (l & 3) * 2;
    #pragma unroll
    for (int mf = 0; mf < 4; mf++) {
        int r = row0 + mf * 16;
        int gr = m_tile * TILE_M + r;
        float bias_r0 = fsq[r];
        float bias_r1 = fsq[r + 8];
        float* o0 = out + (size_t)gr * NCLASS;
        float* o1 = out + (size_t)(gr + 8) * NCLASS;
        #pragma unroll
        for (int nf = 0; nf < 4; nf++) {
            int c = col0 + nf * 8;
            int gc = n_tile * TILE_N + c;
            if (gc < NCLASS) {
                float cs0 = csq[c], cs1 = csq[c + 1];
                float2 v0 = make_float2(acc[mf][nf][0] + bias_r0 + cs0,
                                        acc[mf][nf][1] + bias_r0 + cs1);
                float2 v1 = make_float2(acc[mf][nf][2] + bias_r1 + cs0,
                                        acc[mf][nf][3] + bias_r1 + cs1);
                *reinterpret_cast<float2*>(o0 + gc) = v0;
                *reinterpret_cast<float2*>(o1 + gc) = v1;
            }
        }
    }
}

// ---------------- harness entry ----------------
extern "C" void kernel_launch(void* const* d_in, const int* in_sizes, int n_in,
                              void* d_out, int out_size) {
    const float* feat = (const float*)d_in[0];
    const float* cent = (const float*)d_in[1];
    if (n_in >= 2 && in_sizes[0] != BATCH * FEAT) {
        feat = (const float*)d_in[1];
        cent = (const float*)d_in[0];
    }
    float* out = (float*)d_out;

    cudaFuncSetAttribute(lda_gemm, cudaFuncAttributeMaxDynamicSharedMemorySize, GEMM_SMEM);

    prep_all<<<(BATCH + NCLASS_PAD) / 2, 256>>>(feat, cent);
    lda_gemm<<<M_TILES * N_TILES, 256, GEMM_SMEM>>>(out);
}

// round 17
// speedup vs baseline: 1.0261x; 1.0261x over previous
#include <cuda_runtime.h>
#include <cuda_bf16.h>
#include <cstdint>

// ---------------- problem constants ----------------
#define BATCH       4096
#define NCLASS      10000
#define NCLASS_PAD  10112           // 79 * 128: minimal cover of NCLASS
#define FEAT        1024

#define TILE_M      128
#define TILE_N      128
#define K_STAGE     64
#define N_STAGES    3
#define K_ITERS     (FEAT / K_STAGE)   // 16

#define A_STAGE_BYTES (TILE_M * K_STAGE * 2)   // 16384
#define B_STAGE_BYTES (TILE_N * K_STAGE * 2)   // 16384
#define STAGE_BYTES   (A_STAGE_BYTES + B_STAGE_BYTES) // 32768

#define M_TILES (BATCH / TILE_M)        // 32
#define N_TILES (NCLASS_PAD / TILE_N)   // 79

// SMEM control offsets
#define OFF_FULL   0      // 3 barriers
#define OFF_EMPTY  32     // 3 barriers
#define OFF_FSQ    64     // 128 floats
#define OFF_CSQ    576    // 128 floats
#define CTRL_BYTES 2048
#define GEMM_SMEM  (CTRL_BYTES + 1024 + N_STAGES * STAGE_BYTES)  // 101376 -> 2 CTAs/SM

// ---------------- device scratch ----------------
__device__ __align__(1024) unsigned char g_feat_bf16[(size_t)M_TILES * K_ITERS * A_STAGE_BYTES]; // 8 MB
__device__ __align__(1024) unsigned char g_cent_bf16[(size_t)N_TILES * K_ITERS * B_STAGE_BYTES]; // ~19.8 MB
__device__ float g_feat_sq[BATCH];
__device__ float g_cent_sq[NCLASS_PAD];

// ---------------- PTX helpers ----------------
__device__ __forceinline__ uint32_t smem_u32(const void* p) {
    uint32_t a;
    asm("{ .reg .u64 t; cvta.to.shared.u64 t, %1; cvt.u32.u64 %0, t; }" : "=r"(a) : "l"(p));
    return a;
}

#define MBARRIER_INIT(addr, cnt) \
    asm volatile("mbarrier.init.shared.b64 [%0], %1;" :: "r"((uint32_t)(addr)), "r"((uint32_t)(cnt)) : "memory")

#define MBARRIER_EXPECT_TX(addr, bytes) \
    asm volatile("mbarrier.arrive.expect_tx.shared.b64 _, [%0], %1;" :: "r"((uint32_t)(addr)), "r"((uint32_t)(bytes)) : "memory")

#define MBARRIER_ARRIVE(addr) \
    asm volatile("mbarrier.arrive.shared.b64 _, [%0];" :: "r"((uint32_t)(addr)) : "memory")

#define MBARRIER_WAIT_PARITY(addr, parity) do {                                   \
    uint32_t _m = (uint32_t)(addr); uint32_t _p = (uint32_t)(parity);             \
    asm volatile(                                                                 \
        "{\n\t.reg .pred P1;\n\t"                                                 \
        "WAIT_LOOP_%=:\n\t"                                                       \
        "mbarrier.try_wait.parity.acquire.cta.shared::cta.b64 P1, [%0], %1, 0x989680;\n\t" \
        "@P1 bra.uni WAIT_DONE_%=;\n\t"                                           \
        "bra.uni WAIT_LOOP_%=;\n\t"                                               \
        "WAIT_DONE_%=:\n\t}"                                                      \
        :: "r"(_m), "r"(_p) : "memory");                                          \
} while (0)

#define FENCE_PROXY_ASYNC() asm volatile("fence.proxy.async.shared::cta;" ::: "memory")

__device__ __forceinline__ void bulk_g2s(uint32_t dst, const void* src, uint32_t bytes, uint32_t mbar) {
    asm volatile(
        "cp.async.bulk.shared::cluster.global.mbarrier::complete_tx::bytes [%0], [%1], %2, [%3];"
        :: "r"(dst), "l"(src), "r"(bytes), "r"(mbar) : "memory");
}

#define LDSM_X4(r, addr) \
    asm volatile("ldmatrix.sync.aligned.m8n8.x4.shared.b16 {%0,%1,%2,%3}, [%4];" \
                 : "=r"((r)[0]), "=r"((r)[1]), "=r"((r)[2]), "=r"((r)[3]) : "r"(addr))

#define MMA16816(d, a, b0, b1) \
    asm volatile("mma.sync.aligned.m16n8k16.row.col.f32.bf16.bf16.f32 " \
                 "{%0,%1,%2,%3}, {%4,%5,%6,%7}, {%8,%9}, {%0,%1,%2,%3};" \
                 : "+f"((d)[0]), "+f"((d)[1]), "+f"((d)[2]), "+f"((d)[3]) \
                 : "r"((a)[0]), "r"((a)[1]), "r"((a)[2]), "r"((a)[3]), "r"(b0), "r"(b1))

__device__ __forceinline__ uint32_t sw128(uint32_t off) { return off ^ ((off >> 3) & 0x70); }

// ---------------- prep: 2 rows/block, 8 bf16 per thread, single STG.128 ----------------
__global__ void __launch_bounds__(256) prep_all(const float* __restrict__ feat,
                                                const float* __restrict__ cent) {
    __shared__ float red[8];
    int t = threadIdx.x;
    int lrow = t >> 7;          // 0..1: row within block (4 warps per row)
    int tt = t & 127;           // thread within row; handles 8 consecutive floats
    int blk = blockIdx.x;
    bool is_feat = blk < (BATCH / 2);
    int r = is_feat ? (blk * 2 + lrow) : ((blk - BATCH / 2) * 2 + lrow);
    const float* src = is_feat ? feat : cent;
    bool valid = is_feat || (r < NCLASS);

    int k = tt * 8;
    float4 v0 = make_float4(0.f, 0.f, 0.f, 0.f), v1 = v0;
    if (valid) {
        const float4* p = reinterpret_cast<const float4*>(src + (size_t)r * FEAT + k);
        v0 = p[0];
        v1 = p[1];
    }
    float s2 = v0.x * v0.x + v0.y * v0.y + v0.z * v0.z + v0.w * v0.w
             + v1.x * v1.x + v1.y * v1.y + v1.z * v1.z + v1.w * v1.w;

    uint4 wv;
    {
        __nv_bfloat162 p01 = __float22bfloat162_rn(make_float2(v0.x, v0.y));
        __nv_bfloat162 p23 = __float22bfloat162_rn(make_float2(v0.z, v0.w));
        __nv_bfloat162 p45 = __float22bfloat162_rn(make_float2(v1.x, v1.y));
        __nv_bfloat162 p67 = __float22bfloat162_rn(make_float2(v1.z, v1.w));
        wv.x = *reinterpret_cast<unsigned int*>(&p01);
        wv.y = *reinterpret_cast<unsigned int*>(&p23);
        wv.z = *reinterpret_cast<unsigned int*>(&p45);
        wv.w = *reinterpret_cast<unsigned int*>(&p67);
    }

    int sgm = k >> 6, c = k & 63;
    uint32_t off = sw128((uint32_t)((r & 127) * 128 + c * 2));  // 16B-aligned; sw128 preserves 16B chunks
    if (is_feat) {
        size_t b = ((size_t)(r >> 7) * K_ITERS + sgm) * (size_t)A_STAGE_BYTES;
        *reinterpret_cast<uint4*>(g_feat_bf16 + b + off) = wv;
    } else {
        size_t b = ((size_t)(r >> 7) * K_ITERS + sgm) * (size_t)B_STAGE_BYTES;
        *reinterpret_cast<uint4*>(g_cent_bf16 + b + off) = wv;
    }

    #pragma unroll
    for (int o = 16; o > 0; o >>= 1) s2 += __shfl_down_sync(0xffffffffu, s2, o);
    if ((t & 31) == 0) red[t >> 5] = s2;
    __syncthreads();
    if (tt == 0) {
        float tot = red[4 * lrow] + red[4 * lrow + 1] + red[4 * lrow + 2] + red[4 * lrow + 3];
        if (is_feat) g_feat_sq[r] = -0.5f * tot;
        else g_cent_sq[r] = -0.5f * tot;
    }
}

// ---------------- main GEMM: R13 config (banked best) — UNCHANGED ----------------
__global__ void __launch_bounds__(256, 2) lda_gemm(float* __restrict__ out) {
    extern __shared__ unsigned char smem[];
    uint32_t sb = smem_u32(smem);
    int tid = threadIdx.x, l = tid & 31, w = tid >> 5;
    int warp_m = w >> 2;          // 0..1, 64 rows
    int warp_n = w & 3;           // 0..3, 32 cols
    int bx = blockIdx.x;
    int n_tile = bx % N_TILES;
    int m_tile = bx / N_TILES;

    uint32_t dbase = (sb + CTRL_BYTES + 1023u) & ~1023u;
    const unsigned char* abase = g_feat_bf16 + (size_t)m_tile * K_ITERS * A_STAGE_BYTES;
    const unsigned char* bbase = g_cent_bf16 + (size_t)n_tile * K_ITERS * B_STAGE_BYTES;

    // tid0: init barriers, fence, issue prologue immediately (overlaps bias LDGs)
    if (tid == 0) {
        #pragma unroll
        for (int s = 0; s < N_STAGES; s++) {
            MBARRIER_INIT(sb + OFF_FULL + 8 * s, 1);
            MBARRIER_INIT(sb + OFF_EMPTY + 8 * s, 8);
        }
        FENCE_PROXY_ASYNC();
        #pragma unroll
        for (int s = 0; s < N_STAGES; s++) {
            uint32_t full = sb + OFF_FULL + 8 * s;
            MBARRIER_EXPECT_TX(full, STAGE_BYTES);
            bulk_g2s(dbase + s * STAGE_BYTES, abase + (size_t)s * A_STAGE_BYTES,
                     A_STAGE_BYTES, full);
            bulk_g2s(dbase + s * STAGE_BYTES + A_STAGE_BYTES,
                     bbase + (size_t)s * B_STAGE_BYTES, B_STAGE_BYTES, full);
        }
    }

    float* fsq = reinterpret_cast<float*>(smem + OFF_FSQ);
    float* csq = reinterpret_cast<float*>(smem + OFF_CSQ);
    if (tid < 128) {
        fsq[tid] = g_feat_sq[m_tile * TILE_M + tid];
        csq[tid] = g_cent_sq[n_tile * TILE_N + tid];
    }
    __syncthreads();

    float acc[4][4][4];
    #pragma unroll
    for (int i = 0; i < 4; i++)
        #pragma unroll
        for (int j = 0; j < 4; j++)
            #pragma unroll
            for (int q = 0; q < 4; q++) acc[i][j][q] = 0.f;

    int lrow = l & 15;
    int lcol16 = (l >> 4) * 16;
    int a_row = warp_m * 64 + lrow;
    int b_row = warp_n * 32 + lrow;

    uint32_t a_off[4], b_off[2];
    #pragma unroll
    for (int f = 0; f < 4; f++) {
        int ra = a_row + f * 16;
        a_off[f] = (uint32_t)(ra * 128) + ((uint32_t)lcol16 ^ (uint32_t)((ra & 7) << 4));
    }
    #pragma unroll
    for (int f = 0; f < 2; f++) {
        int rb = b_row + f * 16;
        b_off[f] = (uint32_t)(rb * 128) + ((uint32_t)lcol16 ^ (uint32_t)((rb & 7) << 4));
    }

    int slot = 0, ph = 0;
    #pragma unroll 1
    for (int i = 0; i < K_ITERS; i++) {
        MBARRIER_WAIT_PARITY(sb + OFF_FULL + 8 * slot, ph);

        uint32_t Ab = dbase + slot * STAGE_BYTES;
        uint32_t Bb = Ab + A_STAGE_BYTES;

        #pragma unroll
        for (int ks = 0; ks < 4; ks++) {
            uint32_t kx = (uint32_t)(ks << 5);
            uint32_t afr[4][4], bfr[2][4];
            #pragma unroll
            for (int f = 0; f < 4; f++) LDSM_X4(afr[f], Ab + (a_off[f] ^ kx));
            #pragma unroll
            for (int f = 0; f < 2; f++) LDSM_X4(bfr[f], Bb + (b_off[f] ^ kx));
            #pragma unroll
            for (int nf2 = 0; nf2 < 2; nf2++) {
                #pragma unroll
                for (int mf = 0; mf < 4; mf++) {
                    MMA16816(acc[mf][nf2 * 2 + 0], afr[mf], bfr[nf2][0], bfr[nf2][2]);
                    MMA16816(acc[mf][nf2 * 2 + 1], afr[mf], bfr[nf2][1], bfr[nf2][3]);
                }
            }
        }
        if (l == 0) MBARRIER_ARRIVE(sb + OFF_EMPTY + 8 * slot);

        if (tid == 0 && i + N_STAGES < K_ITERS) {
            int j = i + N_STAGES;
            MBARRIER_WAIT_PARITY(sb + OFF_EMPTY + 8 * slot, ph);
            uint32_t full = sb + OFF_FULL + 8 * slot;
            MBARRIER_EXPECT_TX(full, STAGE_BYTES);
            bulk_g2s(dbase + slot * STAGE_BYTES, abase + (size_t)j * A_STAGE_BYTES,
                     A_STAGE_BYTES, full);
            bulk_g2s(dbase + slot * STAGE_BYTES + A_STAGE_BYTES,
                     bbase + (size_t)j * B_STAGE_BYTES, B_STAGE_BYTES, full);
        }
        if (++slot == N_STAGES) { slot = 0; ph ^= 1; }
    }

    // epilogue: add fused norm biases, store
    int row0 = warp_m * 64 + (l >> 2);
    int col0 = warp_n * 32 + (l & 3) * 2;
    #pragma unroll
    for (int mf = 0; mf < 4; mf++) {
        int r = row0 + mf * 16;
        int gr = m_tile * TILE_M + r;
        float bias_r0 = fsq[r];
        float bias_r1 = fsq[r + 8];
        float* o0 = out + (size_t)gr * NCLASS;
        float* o1 = out + (size_t)(gr + 8) * NCLASS;
        #pragma unroll
        for (int nf = 0; nf < 4; nf++) {
            int c = col0 + nf * 8;
            int gc = n_tile * TILE_N + c;
            if (gc < NCLASS) {
                float cs0 = csq[c], cs1 = csq[c + 1];
                float2 v0 = make_float2(acc[mf][nf][0] + bias_r0 + cs0,
                                        acc[mf][nf][1] + bias_r0 + cs1);
                float2 v1 = make_float2(acc[mf][nf][2] + bias_r1 + cs0,
                                        acc[mf][nf][3] + bias_r1 + cs1);
                *reinterpret_cast<float2*>(o0 + gc) = v0;
                *reinterpret_cast<float2*>(o1 + gc) = v1;
            }
        }
    }
}

// ---------------- harness entry ----------------
extern "C" void kernel_launch(void* const* d_in, const int* in_sizes, int n_in,
                              void* d_out, int out_size) {
    const float* feat = (const float*)d_in[0];
    const float* cent = (const float*)d_in[1];
    if (n_in >= 2 && in_sizes[0] != BATCH * FEAT) {
        feat = (const float*)d_in[1];
        cent = (const float*)d_in[0];
    }
    float* out = (float*)d_out;

    cudaFuncSetAttribute(lda_gemm, cudaFuncAttributeMaxDynamicSharedMemorySize, GEMM_SMEM);

    prep_all<<<(BATCH + NCLASS_PAD) / 2, 256>>>(feat, cent);
    lda_gemm<<<M_TILES * N_TILES, 256, GEMM_SMEM>>>(out);
}